// round 16
// baseline (speedup 1.0000x reference)
#include <cuda_runtime.h>
#include <cuda_bf16.h>
#include <math.h>

#define NN   50000
#define EE   800000
#define DIN  128
#define DHID 128
#define DOUT 64
#define BN_EPS 1e-5f

// ---------------- scratch (device globals) ----------------------------------
__device__ __align__(16) float g_h1[NN * DHID];   // x @ W1 + b1
__device__ __align__(16) float g_h2[NN * DHID];   // propagate(h1)
__device__ __align__(16) float g_g2[NN * DOUT];   // act(h2) @ W2 + b2
__device__ int   g_cnt[NN];
__device__ int   g_cur[NN];
__device__ int   g_off[NN + 1];
__device__ int   g_csr_row[EE];                   // source per edge, grouped by dest
__device__ __align__(16) float g_dis[NN];
__device__ __align__(16) float g_bnsum[2 * DHID];

// ---------------- init: zero cnt, cur, bnsum --------------------------------
__global__ void init_kernel(int N) {
    int idx = blockIdx.x * blockDim.x + threadIdx.x;
    if (idx < N) { g_cnt[idx] = 0; g_cur[idx] = 0; }
    if (idx < 2 * DHID) g_bnsum[idx] = 0.f;
}

// ---------------- degree histogram ------------------------------------------
__global__ void count_deg_kernel(const int* __restrict__ ei, int E) {
    int e = blockIdx.x * blockDim.x + threadIdx.x;
    if (e < E) atomicAdd(&g_cnt[ei[E + e]], 1);
}

// ---------------- parallel deg^-1/2 -----------------------------------------
__global__ void dis_kernel(int N) {
    int i = blockIdx.x * blockDim.x + threadIdx.x;
    if (i < N) g_dis[i] = rsqrtf((float)(g_cnt[i] + 1));  // +1 self loop
}

// ---------------- exclusive scan over g_cnt -> g_off (offsets ONLY) ---------
__global__ __launch_bounds__(1024) void scan_kernel(int N) {
    __shared__ int ssum[1024];
    int t = threadIdx.x;
    int chunk = (N + 1023) >> 10;
    int s0 = t * chunk, s1 = min(N, s0 + chunk);
    int s = 0;
    for (int i = s0; i < s1; i++) s += g_cnt[i];
    ssum[t] = s;
    __syncthreads();
    for (int off = 1; off < 1024; off <<= 1) {
        int v = (t >= off) ? ssum[t - off] : 0;
        __syncthreads();
        ssum[t] += v;
        __syncthreads();
    }
    int base = (t > 0) ? ssum[t - 1] : 0;
    for (int i = s0; i < s1; i++) { g_off[i] = base; base += g_cnt[i]; }
    if (t == 1023) g_off[N] = ssum[1023];
}

// ---------------- CSR fill: group edges by destination ----------------------
__global__ void fill_csr_kernel(const int* __restrict__ ei, int E) {
    int e = blockIdx.x * blockDim.x + threadIdx.x;
    if (e < E) {
        int c = ei[E + e];
        int pos = g_off[c] + atomicAdd(&g_cur[c], 1);
        g_csr_row[pos] = ei[e];
    }
}

// ---------------- GEMM1: g_h1 = x @ W1 + b1 (64x128 tile, W prefetch) -------
__global__ __launch_bounds__(256) void gemm1_kernel(
    const float* __restrict__ x, const float* __restrict__ W1,
    const float* __restrict__ b1, int N)
{
    __shared__ float xs[64 * 128];
    int brow = blockIdx.x * 64;
    int tid = threadIdx.x;

    const float4* xg = (const float4*)(x + (size_t)brow * 128);
    for (int j = tid; j < 64 * 32; j += 256) {
        int rr = j >> 5;
        float4 v = (brow + rr < N) ? xg[j] : make_float4(0.f, 0.f, 0.f, 0.f);
        ((float4*)xs)[j] = v;
    }
    __syncthreads();

    int tx = tid & 31;   // 32 col groups x 4 cols
    int ty = tid >> 5;   // 8 row groups x 8 rows
    float acc[8][4];
#pragma unroll
    for (int i = 0; i < 8; i++)
#pragma unroll
        for (int j = 0; j < 4; j++) acc[i][j] = 0.f;

    // software pipeline: preload chunk k=0, prefetch k+4 while computing k
    float4 nw0 = *(const float4*)(W1 + (size_t)0 * 128 + tx * 4);
    float4 nw1 = *(const float4*)(W1 + (size_t)1 * 128 + tx * 4);
    float4 nw2 = *(const float4*)(W1 + (size_t)2 * 128 + tx * 4);
    float4 nw3 = *(const float4*)(W1 + (size_t)3 * 128 + tx * 4);

    for (int k = 0; k < 128; k += 4) {
        float4 w0 = nw0, w1 = nw1, w2 = nw2, w3 = nw3;
        if (k + 4 < 128) {
            nw0 = *(const float4*)(W1 + (size_t)(k + 4) * 128 + tx * 4);
            nw1 = *(const float4*)(W1 + (size_t)(k + 5) * 128 + tx * 4);
            nw2 = *(const float4*)(W1 + (size_t)(k + 6) * 128 + tx * 4);
            nw3 = *(const float4*)(W1 + (size_t)(k + 7) * 128 + tx * 4);
        }
#pragma unroll
        for (int i = 0; i < 8; i++) {
            float4 a = *(const float4*)(xs + (ty * 8 + i) * 128 + k);  // LDS.128 bcast
            acc[i][0] += a.x * w0.x + a.y * w1.x + a.z * w2.x + a.w * w3.x;
            acc[i][1] += a.x * w0.y + a.y * w1.y + a.z * w2.y + a.w * w3.y;
            acc[i][2] += a.x * w0.z + a.y * w1.z + a.z * w2.z + a.w * w3.z;
            acc[i][3] += a.x * w0.w + a.y * w1.w + a.z * w2.w + a.w * w3.w;
        }
    }
    float4 bb = *(const float4*)(b1 + tx * 4);
#pragma unroll
    for (int i = 0; i < 8; i++) {
        int grow = brow + ty * 8 + i;
        if (grow < N) {
            float4 o = make_float4(acc[i][0] + bb.x, acc[i][1] + bb.y,
                                   acc[i][2] + bb.z, acc[i][3] + bb.w);
            *(float4*)(g_h1 + (size_t)grow * 128 + tx * 4) = o;
        }
    }
}

// ---------------- propagate 1 (gather): g_h2[c] = sum w * g_h1[r] -----------
__global__ __launch_bounds__(256) void prop1_gather_kernel(int N) {
    int c = (blockIdx.x * blockDim.x + threadIdx.x) >> 5;
    int lane = threadIdx.x & 31;
    if (c >= N) return;
    float dc = g_dis[c];
    const float4* h1 = (const float4*)g_h1;

    float4 sv = h1[(size_t)c * 32 + lane];   // self loop
    float ws = dc * dc;
    float ax = sv.x * ws, ay = sv.y * ws, az = sv.z * ws, aw = sv.w * ws;

    int j = g_off[c], e = g_off[c + 1];
    for (; j + 1 < e; j += 2) {
        int r0 = g_csr_row[j], r1 = g_csr_row[j + 1];
        float w0 = dc * g_dis[r0], w1 = dc * g_dis[r1];
        float4 v0 = h1[(size_t)r0 * 32 + lane];
        float4 v1 = h1[(size_t)r1 * 32 + lane];
        ax += w0 * v0.x + w1 * v1.x;
        ay += w0 * v0.y + w1 * v1.y;
        az += w0 * v0.z + w1 * v1.z;
        aw += w0 * v0.w + w1 * v1.w;
    }
    if (j < e) {
        int r0 = g_csr_row[j];
        float w0 = dc * g_dis[r0];
        float4 v0 = h1[(size_t)r0 * 32 + lane];
        ax += w0 * v0.x; ay += w0 * v0.y; az += w0 * v0.z; aw += w0 * v0.w;
    }
    ((float4*)g_h2)[(size_t)c * 32 + lane] = make_float4(ax, ay, az, aw);
}

// ---------------- BN stats over rows ---------------------------------------
__global__ void bn_stats_kernel(int N) {
    int c = threadIdx.x & 127;
    int part = threadIdx.x >> 7;
    int rows_per_block = (N + gridDim.x - 1) / gridDim.x;
    int r0 = blockIdx.x * rows_per_block;
    int r1 = min(N, r0 + rows_per_block);
    float s = 0.f, q = 0.f;
    for (int r = r0 + part; r < r1; r += 2) {
        float v = g_h2[(size_t)r * 128 + c];
        s += v; q += v * v;
    }
    atomicAdd(&g_bnsum[c], s);
    atomicAdd(&g_bnsum[128 + c], q);
}

// ---------------- GEMM2: g_g2 = relu(bn(g_h2)) @ W2 + b2 (fused finalize) ---
__global__ __launch_bounds__(256) void gemm2_kernel(
    const float* __restrict__ W2, const float* __restrict__ b2,
    const float* __restrict__ gamma, const float* __restrict__ beta, int N)
{
    __shared__ float hs[64 * 132];
    __shared__ float s_scale[128], s_shift[128];
    int brow = blockIdx.x * 64;
    int tid = threadIdx.x;

    if (tid < 128) {
        float invN = 1.f / (float)N;
        float mu = g_bnsum[tid] * invN;
        float var = fmaxf(g_bnsum[128 + tid] * invN - mu * mu, 0.f);
        float rs = rsqrtf(var + BN_EPS);
        float sc = rs * gamma[tid];
        s_scale[tid] = sc;
        s_shift[tid] = beta[tid] - mu * sc;
    }
    __syncthreads();

    for (int j = tid; j < 64 * 32; j += 256) {
        int rr = j >> 5, c4 = j & 31;
        int grow = brow + rr;
        float4 v = make_float4(0.f, 0.f, 0.f, 0.f);
        if (grow < N) {
            v = *(const float4*)(g_h2 + (size_t)grow * 128 + c4 * 4);
            float4 sc = *(const float4*)(s_scale + c4 * 4);
            float4 sh = *(const float4*)(s_shift + c4 * 4);
            v.x = fmaxf(v.x * sc.x + sh.x, 0.f);
            v.y = fmaxf(v.y * sc.y + sh.y, 0.f);
            v.z = fmaxf(v.z * sc.z + sh.z, 0.f);
            v.w = fmaxf(v.w * sc.w + sh.w, 0.f);
        }
        *(float4*)(hs + rr * 132 + c4 * 4) = v;
    }
    __syncthreads();

    int c4 = tid & 15;   // 16 col groups x 4 cols = 64
    int rg = tid >> 4;   // 16 row groups x 4 rows = 64
    float acc[4][4];
#pragma unroll
    for (int i = 0; i < 4; i++)
#pragma unroll
        for (int j = 0; j < 4; j++) acc[i][j] = 0.f;

    float4 nw0 = *(const float4*)(W2 + (size_t)0 * 64 + c4 * 4);
    float4 nw1 = *(const float4*)(W2 + (size_t)1 * 64 + c4 * 4);
    float4 nw2 = *(const float4*)(W2 + (size_t)2 * 64 + c4 * 4);
    float4 nw3 = *(const float4*)(W2 + (size_t)3 * 64 + c4 * 4);

    for (int k = 0; k < 128; k += 4) {
        float4 w0 = nw0, w1 = nw1, w2 = nw2, w3 = nw3;
        if (k + 4 < 128) {
            nw0 = *(const float4*)(W2 + (size_t)(k + 4) * 64 + c4 * 4);
            nw1 = *(const float4*)(W2 + (size_t)(k + 5) * 64 + c4 * 4);
            nw2 = *(const float4*)(W2 + (size_t)(k + 6) * 64 + c4 * 4);
            nw3 = *(const float4*)(W2 + (size_t)(k + 7) * 64 + c4 * 4);
        }
#pragma unroll
        for (int i = 0; i < 4; i++) {
            float4 a = *(const float4*)(hs + (rg * 4 + i) * 132 + k);
            acc[i][0] += a.x * w0.x + a.y * w1.x + a.z * w2.x + a.w * w3.x;
            acc[i][1] += a.x * w0.y + a.y * w1.y + a.z * w2.y + a.w * w3.y;
            acc[i][2] += a.x * w0.z + a.y * w1.z + a.z * w2.z + a.w * w3.z;
            acc[i][3] += a.x * w0.w + a.y * w1.w + a.z * w2.w + a.w * w3.w;
        }
    }
    float4 bb = *(const float4*)(b2 + c4 * 4);
#pragma unroll
    for (int i = 0; i < 4; i++) {
        int grow = brow + rg * 4 + i;
        if (grow < N) {
            float4 o = make_float4(acc[i][0] + bb.x, acc[i][1] + bb.y,
                                   acc[i][2] + bb.z, acc[i][3] + bb.w);
            *(float4*)(g_g2 + (size_t)grow * 64 + c4 * 4) = o;
        }
    }
}

// ---------------- propagate 2 + log_softmax fused; plain stores to d_out ----
__global__ __launch_bounds__(256) void prop2_softmax_kernel(
    float* __restrict__ out, int N)
{
    int c = (blockIdx.x * blockDim.x + threadIdx.x) >> 5;
    int lane = threadIdx.x & 31;
    if (c >= N) return;
    float dc = g_dis[c];
    const float2* gg = (const float2*)g_g2;

    float2 sv = gg[(size_t)c * 32 + lane];
    float ws = dc * dc;
    float ax = sv.x * ws, ay = sv.y * ws;

    int j = g_off[c], e = g_off[c + 1];
    for (; j + 1 < e; j += 2) {
        int r0 = g_csr_row[j], r1 = g_csr_row[j + 1];
        float w0 = dc * g_dis[r0], w1 = dc * g_dis[r1];
        float2 v0 = gg[(size_t)r0 * 32 + lane];
        float2 v1 = gg[(size_t)r1 * 32 + lane];
        ax += w0 * v0.x + w1 * v1.x;
        ay += w0 * v0.y + w1 * v1.y;
    }
    if (j < e) {
        int r0 = g_csr_row[j];
        float w0 = dc * g_dis[r0];
        float2 v0 = gg[(size_t)r0 * 32 + lane];
        ax += w0 * v0.x; ay += w0 * v0.y;
    }

    float m = fmaxf(ax, ay);
#pragma unroll
    for (int off = 16; off > 0; off >>= 1)
        m = fmaxf(m, __shfl_xor_sync(0xFFFFFFFFu, m, off));
    float s = expf(ax - m) + expf(ay - m);
#pragma unroll
    for (int off = 16; off > 0; off >>= 1)
        s += __shfl_xor_sync(0xFFFFFFFFu, s, off);
    float l = m + logf(s);
    *(float2*)(out + (size_t)c * 64 + lane * 2) = make_float2(ax - l, ay - l);
}

// ---------------- launch: CSR build forked parallel to GEMM1 ----------------
extern "C" void kernel_launch(void* const* d_in, const int* in_sizes, int n_in,
                              void* d_out, int out_size) {
    const float* x     = (const float*)d_in[0];
    const float* W1    = (const float*)d_in[1];
    const float* b1    = (const float*)d_in[2];
    const float* gamma = (const float*)d_in[3];
    const float* beta  = (const float*)d_in[4];
    const float* W2    = (const float*)d_in[5];
    const float* b2    = (const float*)d_in[6];
    const int*   ei    = (const int*)d_in[7];

    int N = in_sizes[0] / DIN;
    int E = in_sizes[7] / 2;
    float* out = (float*)d_out;

    // fork a side stream off the (captured) default stream for the CSR chain
    cudaStream_t s2;
    cudaStreamCreateWithFlags(&s2, cudaStreamNonBlocking);
    cudaEvent_t evFork, evJoin;
    cudaEventCreateWithFlags(&evFork, cudaEventDisableTiming);
    cudaEventCreateWithFlags(&evJoin, cudaEventDisableTiming);

    cudaEventRecord(evFork, 0);
    cudaStreamWaitEvent(s2, evFork, 0);

    // --- branch A (s2): CSR build, depends only on edge_index ---
    init_kernel<<<(N + 255) / 256, 256, 0, s2>>>(N);
    count_deg_kernel<<<(E + 255) / 256, 256, 0, s2>>>(ei, E);
    scan_kernel<<<1, 1024, 0, s2>>>(N);
    dis_kernel<<<(N + 255) / 256, 256, 0, s2>>>(N);
    fill_csr_kernel<<<(E + 255) / 256, 256, 0, s2>>>(ei, E);
    cudaEventRecord(evJoin, s2);

    // --- branch B (default stream): GEMM1, depends only on x/W1/b1 ---
    gemm1_kernel<<<(N + 63) / 64, 256>>>(x, W1, b1, N);

    // join: everything after needs both branches
    cudaStreamWaitEvent(0, evJoin, 0);

    {
        int blocks = (int)(((long long)N * 32 + 255) / 256);
        prop1_gather_kernel<<<blocks, 256>>>(N);
    }

    bn_stats_kernel<<<256, 256>>>(N);

    gemm2_kernel<<<(N + 63) / 64, 256>>>(W2, b2, gamma, beta, N);

    {
        int blocks = (int)(((long long)N * 32 + 255) / 256);
        prop2_softmax_kernel<<<blocks, 256>>>(out, N);
    }

    cudaEventDestroy(evFork);
    cudaEventDestroy(evJoin);
    cudaStreamDestroy(s2);
}

// round 17
// speedup vs baseline: 1.2027x; 1.2027x over previous
#include <cuda_runtime.h>
#include <cuda_bf16.h>
#include <math.h>

#define NN   50000
#define EE   800000
#define DIN  128
#define DHID 128
#define DOUT 64
#define BN_EPS 1e-5f

// ---------------- scratch (device globals) ----------------------------------
__device__ __align__(16) float g_h1[NN * DHID];   // x @ W1 + b1
__device__ __align__(16) float g_h2[NN * DHID];   // propagate(h1)
__device__ __align__(16) float g_g2[NN * DOUT];   // act(h2) @ W2 + b2
__device__ int   g_cnt[NN];
__device__ int   g_cur[NN];
__device__ int   g_off[NN + 1];
__device__ int   g_csr_row[EE];                   // source per edge, grouped by dest
__device__ __align__(16) float g_dis[NN];
__device__ __align__(16) float g_bnsum[2 * DHID];

// ---------------- tf32 mma helpers ------------------------------------------
__device__ __forceinline__ unsigned f2tf32(float f) {
    unsigned r;
    asm("cvt.rna.tf32.f32 %0, %1;" : "=r"(r) : "f"(f));
    return r;
}
__device__ __forceinline__ void mma_tf32(float* c,
    unsigned a0, unsigned a1, unsigned a2, unsigned a3,
    unsigned b0, unsigned b1) {
    asm volatile(
        "mma.sync.aligned.m16n8k8.row.col.f32.tf32.tf32.f32 "
        "{%0,%1,%2,%3}, {%4,%5,%6,%7}, {%8,%9}, {%0,%1,%2,%3};"
        : "+f"(c[0]), "+f"(c[1]), "+f"(c[2]), "+f"(c[3])
        : "r"(a0), "r"(a1), "r"(a2), "r"(a3), "r"(b0), "r"(b1));
}

// ---------------- init: zero cnt, cur, bnsum --------------------------------
__global__ void init_kernel(int N) {
    int idx = blockIdx.x * blockDim.x + threadIdx.x;
    if (idx < N) { g_cnt[idx] = 0; g_cur[idx] = 0; }
    if (idx < 2 * DHID) g_bnsum[idx] = 0.f;
}

// ---------------- degree histogram ------------------------------------------
__global__ void count_deg_kernel(const int* __restrict__ ei, int E) {
    int e = blockIdx.x * blockDim.x + threadIdx.x;
    if (e < E) atomicAdd(&g_cnt[ei[E + e]], 1);
}

// ---------------- parallel deg^-1/2 -----------------------------------------
__global__ void dis_kernel(int N) {
    int i = blockIdx.x * blockDim.x + threadIdx.x;
    if (i < N) g_dis[i] = rsqrtf((float)(g_cnt[i] + 1));  // +1 self loop
}

// ---------------- exclusive scan over g_cnt -> g_off (offsets ONLY) ---------
__global__ __launch_bounds__(1024) void scan_kernel(int N) {
    __shared__ int ssum[1024];
    int t = threadIdx.x;
    int chunk = (N + 1023) >> 10;
    int s0 = t * chunk, s1 = min(N, s0 + chunk);
    int s = 0;
    for (int i = s0; i < s1; i++) s += g_cnt[i];
    ssum[t] = s;
    __syncthreads();
    for (int off = 1; off < 1024; off <<= 1) {
        int v = (t >= off) ? ssum[t - off] : 0;
        __syncthreads();
        ssum[t] += v;
        __syncthreads();
    }
    int base = (t > 0) ? ssum[t - 1] : 0;
    for (int i = s0; i < s1; i++) { g_off[i] = base; base += g_cnt[i]; }
    if (t == 1023) g_off[N] = ssum[1023];
}

// ---------------- CSR fill: group edges by destination ----------------------
__global__ void fill_csr_kernel(const int* __restrict__ ei, int E) {
    int e = blockIdx.x * blockDim.x + threadIdx.x;
    if (e < E) {
        int c = ei[E + e];
        int pos = g_off[c] + atomicAdd(&g_cur[c], 1);
        g_csr_row[pos] = ei[e];
    }
}

// ---------------- GEMM1 (tf32 mma): g_h1 = x @ W1 + b1 ----------------------
// block: 256 thr = 8 warps; warp = (m_group 0..3) x (n_half 0..1)
// block tile: 64 rows x 128 cols; warp tile: 16 rows x 64 cols (8 n-frags)
__global__ __launch_bounds__(256) void gemm1_kernel(
    const float* __restrict__ x, const float* __restrict__ W1,
    const float* __restrict__ b1, int N)
{
    int tid  = threadIdx.x;
    int warp = tid >> 5, lane = tid & 31;
    int gid  = lane >> 2, tig = lane & 3;
    int mg   = warp >> 1;
    int nh   = (warp & 1) * 64;
    int row0 = blockIdx.x * 64 + mg * 16;

    int ra = min(row0 + gid,     N - 1);
    int rb = min(row0 + gid + 8, N - 1);
    const float* xa = x + (size_t)ra * 128;
    const float* xb = x + (size_t)rb * 128;

    float c[8][4];
#pragma unroll
    for (int f = 0; f < 8; f++)
#pragma unroll
        for (int q = 0; q < 4; q++) c[f][q] = 0.f;

    for (int k = 0; k < 128; k += 8) {
        unsigned a0 = f2tf32(xa[k + tig]);
        unsigned a1 = f2tf32(xb[k + tig]);
        unsigned a2 = f2tf32(xa[k + tig + 4]);
        unsigned a3 = f2tf32(xb[k + tig + 4]);
#pragma unroll
        for (int f = 0; f < 8; f++) {
            int n = nh + f * 8 + gid;
            unsigned b0 = f2tf32(W1[(size_t)(k + tig)     * 128 + n]);
            unsigned bv = f2tf32(W1[(size_t)(k + tig + 4) * 128 + n]);
            mma_tf32(c[f], a0, a1, a2, a3, b0, bv);
        }
    }

#pragma unroll
    for (int f = 0; f < 8; f++) {
        int col0 = nh + f * 8 + tig * 2;
        float2 bb = *(const float2*)(b1 + col0);
        int r0 = row0 + gid, r1 = row0 + gid + 8;
        if (r0 < N)
            *(float2*)(g_h1 + (size_t)r0 * 128 + col0) =
                make_float2(c[f][0] + bb.x, c[f][1] + bb.y);
        if (r1 < N)
            *(float2*)(g_h1 + (size_t)r1 * 128 + col0) =
                make_float2(c[f][2] + bb.x, c[f][3] + bb.y);
    }
}

// ---------------- propagate 1 (gather): g_h2[c] = sum w * g_h1[r] -----------
__global__ __launch_bounds__(256) void prop1_gather_kernel(int N) {
    int c = (blockIdx.x * blockDim.x + threadIdx.x) >> 5;
    int lane = threadIdx.x & 31;
    if (c >= N) return;
    float dc = g_dis[c];
    const float4* h1 = (const float4*)g_h1;

    float4 sv = h1[(size_t)c * 32 + lane];   // self loop
    float ws = dc * dc;
    float ax = sv.x * ws, ay = sv.y * ws, az = sv.z * ws, aw = sv.w * ws;

    int j = g_off[c], e = g_off[c + 1];
    for (; j + 1 < e; j += 2) {
        int r0 = g_csr_row[j], r1 = g_csr_row[j + 1];
        float w0 = dc * g_dis[r0], w1 = dc * g_dis[r1];
        float4 v0 = h1[(size_t)r0 * 32 + lane];
        float4 v1 = h1[(size_t)r1 * 32 + lane];
        ax += w0 * v0.x + w1 * v1.x;
        ay += w0 * v0.y + w1 * v1.y;
        az += w0 * v0.z + w1 * v1.z;
        aw += w0 * v0.w + w1 * v1.w;
    }
    if (j < e) {
        int r0 = g_csr_row[j];
        float w0 = dc * g_dis[r0];
        float4 v0 = h1[(size_t)r0 * 32 + lane];
        ax += w0 * v0.x; ay += w0 * v0.y; az += w0 * v0.z; aw += w0 * v0.w;
    }
    ((float4*)g_h2)[(size_t)c * 32 + lane] = make_float4(ax, ay, az, aw);
}

// ---------------- BN stats over rows ---------------------------------------
__global__ void bn_stats_kernel(int N) {
    int c = threadIdx.x & 127;
    int part = threadIdx.x >> 7;
    int rows_per_block = (N + gridDim.x - 1) / gridDim.x;
    int r0 = blockIdx.x * rows_per_block;
    int r1 = min(N, r0 + rows_per_block);
    float s = 0.f, q = 0.f;
    for (int r = r0 + part; r < r1; r += 2) {
        float v = g_h2[(size_t)r * 128 + c];
        s += v; q += v * v;
    }
    atomicAdd(&g_bnsum[c], s);
    atomicAdd(&g_bnsum[128 + c], q);
}

// ---------------- GEMM2 (tf32 mma): g_g2 = relu(bn(g_h2)) @ W2 + b2 ---------
// block: 256 thr = 8 warps; warp w handles rows [128*blk + 16w, +16), cols 0..63
__global__ __launch_bounds__(256) void gemm2_kernel(
    const float* __restrict__ W2, const float* __restrict__ b2,
    const float* __restrict__ gamma, const float* __restrict__ beta, int N)
{
    __shared__ float s_scale[128], s_shift[128];
    int tid  = threadIdx.x;
    int warp = tid >> 5, lane = tid & 31;
    int gid  = lane >> 2, tig = lane & 3;
    int row0 = blockIdx.x * 128 + warp * 16;

    if (tid < 128) {
        float invN = 1.f / (float)N;
        float mu = g_bnsum[tid] * invN;
        float var = fmaxf(g_bnsum[128 + tid] * invN - mu * mu, 0.f);
        float rs = rsqrtf(var + BN_EPS);
        float sc = rs * gamma[tid];
        s_scale[tid] = sc;
        s_shift[tid] = beta[tid] - mu * sc;
    }
    __syncthreads();

    int ra = min(row0 + gid,     N - 1);
    int rb = min(row0 + gid + 8, N - 1);
    const float* ha = g_h2 + (size_t)ra * 128;
    const float* hb = g_h2 + (size_t)rb * 128;

    float c[8][4];
#pragma unroll
    for (int f = 0; f < 8; f++)
#pragma unroll
        for (int q = 0; q < 4; q++) c[f][q] = 0.f;

    for (int k = 0; k < 128; k += 8) {
        int k0 = k + tig, k1 = k + tig + 4;
        float sc0 = s_scale[k0], sh0 = s_shift[k0];
        float sc1 = s_scale[k1], sh1 = s_shift[k1];
        unsigned a0 = f2tf32(fmaxf(ha[k0] * sc0 + sh0, 0.f));
        unsigned a1 = f2tf32(fmaxf(hb[k0] * sc0 + sh0, 0.f));
        unsigned a2 = f2tf32(fmaxf(ha[k1] * sc1 + sh1, 0.f));
        unsigned a3 = f2tf32(fmaxf(hb[k1] * sc1 + sh1, 0.f));
#pragma unroll
        for (int f = 0; f < 8; f++) {
            int n = f * 8 + gid;
            unsigned b0 = f2tf32(W2[(size_t)k0 * 64 + n]);
            unsigned bv = f2tf32(W2[(size_t)k1 * 64 + n]);
            mma_tf32(c[f], a0, a1, a2, a3, b0, bv);
        }
    }

#pragma unroll
    for (int f = 0; f < 8; f++) {
        int col0 = f * 8 + tig * 2;
        float2 bb = *(const float2*)(b2 + col0);
        int r0 = row0 + gid, r1 = row0 + gid + 8;
        if (r0 < N)
            *(float2*)(g_g2 + (size_t)r0 * 64 + col0) =
                make_float2(c[f][0] + bb.x, c[f][1] + bb.y);
        if (r1 < N)
            *(float2*)(g_g2 + (size_t)r1 * 64 + col0) =
                make_float2(c[f][2] + bb.x, c[f][3] + bb.y);
    }
}

// ---------------- propagate 2 + log_softmax fused; plain stores to d_out ----
__global__ __launch_bounds__(256) void prop2_softmax_kernel(
    float* __restrict__ out, int N)
{
    int c = (blockIdx.x * blockDim.x + threadIdx.x) >> 5;
    int lane = threadIdx.x & 31;
    if (c >= N) return;
    float dc = g_dis[c];
    const float2* gg = (const float2*)g_g2;

    float2 sv = gg[(size_t)c * 32 + lane];
    float ws = dc * dc;
    float ax = sv.x * ws, ay = sv.y * ws;

    int j = g_off[c], e = g_off[c + 1];
    for (; j + 1 < e; j += 2) {
        int r0 = g_csr_row[j], r1 = g_csr_row[j + 1];
        float w0 = dc * g_dis[r0], w1 = dc * g_dis[r1];
        float2 v0 = gg[(size_t)r0 * 32 + lane];
        float2 v1 = gg[(size_t)r1 * 32 + lane];
        ax += w0 * v0.x + w1 * v1.x;
        ay += w0 * v0.y + w1 * v1.y;
    }
    if (j < e) {
        int r0 = g_csr_row[j];
        float w0 = dc * g_dis[r0];
        float2 v0 = gg[(size_t)r0 * 32 + lane];
        ax += w0 * v0.x; ay += w0 * v0.y;
    }

    float m = fmaxf(ax, ay);
#pragma unroll
    for (int off = 16; off > 0; off >>= 1)
        m = fmaxf(m, __shfl_xor_sync(0xFFFFFFFFu, m, off));
    float s = expf(ax - m) + expf(ay - m);
#pragma unroll
    for (int off = 16; off > 0; off >>= 1)
        s += __shfl_xor_sync(0xFFFFFFFFu, s, off);
    float l = m + logf(s);
    *(float2*)(out + (size_t)c * 64 + lane * 2) = make_float2(ax - l, ay - l);
}

// ---------------- launch: CSR build forked parallel to GEMM1 ----------------
extern "C" void kernel_launch(void* const* d_in, const int* in_sizes, int n_in,
                              void* d_out, int out_size) {
    const float* x     = (const float*)d_in[0];
    const float* W1    = (const float*)d_in[1];
    const float* b1    = (const float*)d_in[2];
    const float* gamma = (const float*)d_in[3];
    const float* beta  = (const float*)d_in[4];
    const float* W2    = (const float*)d_in[5];
    const float* b2    = (const float*)d_in[6];
    const int*   ei    = (const int*)d_in[7];

    int N = in_sizes[0] / DIN;
    int E = in_sizes[7] / 2;
    float* out = (float*)d_out;

    cudaStream_t s2;
    cudaStreamCreateWithFlags(&s2, cudaStreamNonBlocking);
    cudaEvent_t evFork, evJoin;
    cudaEventCreateWithFlags(&evFork, cudaEventDisableTiming);
    cudaEventCreateWithFlags(&evJoin, cudaEventDisableTiming);

    cudaEventRecord(evFork, 0);
    cudaStreamWaitEvent(s2, evFork, 0);

    // --- branch A (s2): CSR build, depends only on edge_index ---
    init_kernel<<<(N + 255) / 256, 256, 0, s2>>>(N);
    count_deg_kernel<<<(E + 255) / 256, 256, 0, s2>>>(ei, E);
    scan_kernel<<<1, 1024, 0, s2>>>(N);
    dis_kernel<<<(N + 255) / 256, 256, 0, s2>>>(N);
    fill_csr_kernel<<<(E + 255) / 256, 256, 0, s2>>>(ei, E);
    cudaEventRecord(evJoin, s2);

    // --- branch B (default stream): GEMM1 (tf32 tensor cores) ---
    gemm1_kernel<<<(N + 63) / 64, 256>>>(x, W1, b1, N);

    cudaStreamWaitEvent(0, evJoin, 0);

    {
        int blocks = (int)(((long long)N * 32 + 255) / 256);
        prop1_gather_kernel<<<blocks, 256>>>(N);
    }

    bn_stats_kernel<<<256, 256>>>(N);

    gemm2_kernel<<<(N + 127) / 128, 256>>>(W2, b2, gamma, beta, N);

    {
        int blocks = (int)(((long long)N * 32 + 255) / 256);
        prop2_softmax_kernel<<<blocks, 256>>>(out, N);
    }

    cudaEventDestroy(evFork);
    cudaEventDestroy(evJoin);
    cudaStreamDestroy(s2);
}